// round 16
// baseline (speedup 1.0000x reference)
#include <cuda_runtime.h>
#include <cuda_bf16.h>
#include <math.h>
#include <cstdint>

#define Hh 128
#define Nn 50000
#define Ee 500000
#define LN_EPS 1e-5f
#define EB 128
#define NT ((Ee + EB - 1) / EB)     // 3907 tiles
#define EGRID 296

// ---------------- scratch ----------------
__device__ __align__(16) __nv_bfloat16 g_P1b[Nn * Hh];
__device__ __align__(16) __nv_bfloat16 g_P2b[Nn * Hh];
__device__ __align__(16) __nv_bfloat16 g_Sb[Nn * Hh];
__device__ float g_self[Nn * Hh];
__device__ float g_agg[Nn * Hh];
__device__ float g_indeg[Nn];
__device__ __align__(16) __nv_bfloat16 g_W2t[256 * 128];
__device__ __align__(16) __nv_bfloat16 g_Wn[512 * 128];
__device__ __align__(16) __nv_bfloat16 g_WAt[128 * 128];   // aggW^T bf16 [n][k]
__device__ float g_bn[512];

// Branchless erf (Abramowitz–Stegun 7.1.26, |err| <= 1.5e-7)
__device__ __forceinline__ float gelu_fast(float x) {
    float z = x * 0.70710678118654752440f;
    float az = fabsf(z);
    float t = __fdividef(1.0f, fmaf(0.3275911f, az, 1.0f));
    float p = t * fmaf(t, fmaf(t, fmaf(t, fmaf(t, 1.061405429f, -1.453152027f),
                                       1.421413741f), -0.284496736f), 0.254829592f);
    float e = __expf(-z * z);
    float erf_abs = fmaf(-p, e, 1.0f);
    float erfv = copysignf(erf_abs, z);
    return 0.5f * x * (1.0f + erfv);
}

__device__ __forceinline__ uint32_t smem_u32(const void* p) {
    uint32_t a;
    asm("{ .reg .u64 t; cvta.to.shared.u64 t, %1; cvt.u32.u64 %0, t; }" : "=r"(a) : "l"(p));
    return a;
}
__device__ __forceinline__ void ldsm_x4(uint32_t* r, uint32_t addr) {
    asm volatile("ldmatrix.sync.aligned.m8n8.x4.shared.b16 {%0,%1,%2,%3}, [%4];"
                 : "=r"(r[0]), "=r"(r[1]), "=r"(r[2]), "=r"(r[3]) : "r"(addr));
}
__device__ __forceinline__ void ldsm_x2(uint32_t* r, uint32_t addr) {
    asm volatile("ldmatrix.sync.aligned.m8n8.x2.shared.b16 {%0,%1}, [%2];"
                 : "=r"(r[0]), "=r"(r[1]) : "r"(addr));
}
__device__ __forceinline__ void mma_bf16(float* c, const uint32_t* a, const uint32_t* b) {
    asm volatile(
        "mma.sync.aligned.m16n8k16.row.col.f32.bf16.bf16.f32 "
        "{%0,%1,%2,%3},{%4,%5,%6,%7},{%8,%9},{%0,%1,%2,%3};"
        : "+f"(c[0]), "+f"(c[1]), "+f"(c[2]), "+f"(c[3])
        : "r"(a[0]), "r"(a[1]), "r"(a[2]), "r"(a[3]), "r"(b[0]), "r"(b[1]));
}
__device__ __forceinline__ uint32_t pack_bf16(float a, float b) {
    __nv_bfloat162 t = __float22bfloat162_rn(make_float2(a, b));
    return *reinterpret_cast<uint32_t*>(&t);
}
__device__ __forceinline__ float2 bf2f(const __nv_bfloat16* p) {
    return __bfloat1622float2(*(const __nv_bfloat162*)p);
}
__device__ __forceinline__ float2 up2(uint32_t v) {
    return __bfloat1622float2(*reinterpret_cast<__nv_bfloat162*>(&v));
}
__device__ __forceinline__ uint32_t badd2(uint32_t a, uint32_t b) {
    __nv_bfloat162 r = __hadd2(*reinterpret_cast<__nv_bfloat162*>(&a),
                               *reinterpret_cast<__nv_bfloat162*>(&b));
    return *reinterpret_cast<uint32_t*>(&r);
}
__device__ __forceinline__ void cp_async16(uint32_t dst, const void* src) {
    asm volatile("cp.async.cg.shared.global [%0], [%1], 16;" :: "r"(dst), "l"(src) : "memory");
}
#define CP_COMMIT() asm volatile("cp.async.commit_group;" ::: "memory")
#define CP_WAIT0()  asm volatile("cp.async.wait_group 0;" ::: "memory")

// ---------------------------------------------------------------------------
// prep + zero fused
// ---------------------------------------------------------------------------
__global__ void prep_zero_kernel(const float* __restrict__ e2W,
                                 const float* __restrict__ e1W,
                                 const float* __restrict__ srcW,
                                 const float* __restrict__ selfW,
                                 const float* __restrict__ srcB,
                                 const float* __restrict__ selfB,
                                 const float* __restrict__ aggW) {
    long i = (long)blockIdx.x * 256 + threadIdx.x;
    const long agg4 = (long)Nn * Hh / 4;
    if (i < agg4) ((float4*)g_agg)[i] = make_float4(0.f, 0.f, 0.f, 0.f);
    else if (i < agg4 + Nn / 4) ((float4*)g_indeg)[i - agg4] = make_float4(0.f, 0.f, 0.f, 0.f);

    if (i < 512 * 128) {
        int n = (int)i >> 7, k = (int)i & 127;
        float v;
        if (n < 128)      v = e1W[k * 128 + n];
        else if (n < 256) v = e1W[(128 + k) * 128 + (n - 128)];
        else if (n < 384) v = srcW[k * 128 + (n - 256)];
        else              v = selfW[k * 128 + (n - 384)];
        g_Wn[i] = __float2bfloat16(v);
    }
    if (i < 256 * 128) {
        int n = (int)i >> 7, k = (int)i & 127;
        g_W2t[i] = __float2bfloat16(e2W[k * 256 + n]);
    }
    if (i < 128 * 128) {
        int n = (int)i >> 7, k = (int)i & 127;
        g_WAt[i] = __float2bfloat16(aggW[k * 128 + n]);
    }
    if (i < 512) {
        g_bn[i] = (i < 256) ? 0.0f : ((i < 384) ? srcB[i - 256] : selfB[i - 384]);
    }
}

// ---------------------------------------------------------------------------
// K1: node projections via bf16 HMMA (unchanged)
// ---------------------------------------------------------------------------
#define NP_SM_A 0
#define NP_SM_B 32768
#define NP_SM_BI 98304
#define NP_SMEM 99328

__global__ void __launch_bounds__(256, 2)
node_pre_mma(const float* __restrict__ h) {
    extern __shared__ char smem[];
    const uint32_t sbm = smem_u32(smem);
    const int tid = threadIdx.x;
    const int lane = tid & 31;
    const int wid = tid >> 5;
    const int tile = blockIdx.x;
    const int half = blockIdx.y;
    float* bi_s = (float*)(smem + NP_SM_BI);

#pragma unroll
    for (int it = 0; it < 8; it++) {
        int idx = tid + it * 256;
        int row = idx >> 4, c = idx & 15;
        int node = tile * 128 + row;
        uint4 w = make_uint4(0u, 0u, 0u, 0u);
        if (node < Nn) {
            const float4* p = (const float4*)(h + (long)node * 128 + c * 8);
            float4 v0 = p[0], v1 = p[1];
            w.x = pack_bf16(v0.x, v0.y); w.y = pack_bf16(v0.z, v0.w);
            w.z = pack_bf16(v1.x, v1.y); w.w = pack_bf16(v1.z, v1.w);
        }
        *(uint4*)(smem + NP_SM_A + row * 256 + ((c ^ (row & 7)) << 4)) = w;
    }
#pragma unroll
    for (int it = 0; it < 16; it++) {
        int idx = tid + it * 256;
        int n = idx >> 4, c = idx & 15;
        uint4 v = *(const uint4*)(g_Wn + (long)(half * 256 + n) * 128 + c * 8);
        *(uint4*)(smem + NP_SM_B + n * 256 + ((c ^ (n & 7)) << 4)) = v;
    }
    if (tid < 256) bi_s[tid] = g_bn[half * 256 + tid];
    __syncthreads();

    uint32_t Af[8][4];
    {
        int ts = lane >> 3;
        int row = wid * 16 + ((ts & 1) << 3) + (lane & 7);
        int rx = row & 7;
        uint32_t rb = sbm + NP_SM_A + row * 256;
#pragma unroll
        for (int kb = 0; kb < 8; kb++) {
            int c = kb * 2 + (ts >> 1);
            ldsm_x4(Af[kb], rb + ((c ^ rx) << 4));
        }
    }

    const int tsel = lane >> 3;
    const int jj_l = tsel >> 1;
    const int kh_l = tsel & 1;
    const int l7 = lane & 7;
    const int r0 = lane >> 2;
    const int cb2 = (lane & 3) * 2;

#pragma unroll 1
    for (int p = 0; p < 16; p++) {
        float C[2][4] = {{0.f,0.f,0.f,0.f},{0.f,0.f,0.f,0.f}};
        const int ng = p * 16 + jj_l * 8 + l7;
#pragma unroll
        for (int kb = 0; kb < 8; kb++) {
            uint32_t Bf[4];
            int c = kb * 2 + kh_l;
            ldsm_x4(Bf, sbm + NP_SM_B + ng * 256 + ((c ^ (ng & 7)) << 4));
            mma_bf16(C[0], Af[kb], Bf);
            mma_bf16(C[1], Af[kb], Bf + 2);
        }
#pragma unroll
        for (int jj = 0; jj < 2; jj++) {
            int nl = (2 * p + jj) * 8 + cb2;
            int n = half * 256 + nl;
            float2 bias = *(const float2*)(bi_s + nl);
            int nm = n & 127;
#pragma unroll
            for (int rh = 0; rh < 2; rh++) {
                int row = wid * 16 + r0 + rh * 8;
                int node = tile * 128 + row;
                if (node < Nn) {
                    float v0 = C[jj][rh * 2] + bias.x;
                    float v1 = C[jj][rh * 2 + 1] + bias.y;
                    if (n < 384) {
                        __nv_bfloat16* dstb = (n < 128) ? g_P1b : (n < 256) ? g_P2b : g_Sb;
                        *(__nv_bfloat162*)(dstb + (long)node * 128 + nm) =
                            __float22bfloat162_rn(make_float2(v0, v1));
                    } else {
                        *(float2*)(g_self + (long)node * 128 + nm) = make_float2(v0, v1);
                    }
                }
            }
        }
    }
}

// ---------------------------------------------------------------------------
// K2: persistent edge kernel — warp-decoupled + warp-local wide PS staging.
// Per tile per warp: stage PS = P1[s]+P2[d] (wide LDG.128 + HADD2) into the
// PS/S region, read into C1 (conflict-free LDS), then reuse region for the
// S cp.async prefetch (consumed in epilogue). No per-tile block syncs.
// smem: B2 65536 @0 ; W1T 4096 @65536 ; EST 4096 @69632 ; b1 512 @73728 ;
//       b2 1024 @74240 ; PS/S 128x272 @75264 (34816) -> 110080
// ---------------------------------------------------------------------------
#define SM_B2   0
#define SM_W1T  65536
#define SM_EST  69632
#define SM_B1   73728
#define SM_B2B  74240
#define SM_S    75264
#define S_STRIDE 272
#define SMEM_EDGE 110080

__global__ void __launch_bounds__(256, 2)
edge_kernel(const float* __restrict__ eattr,
            const int* __restrict__ eidx,
            const float* __restrict__ e1W,
            const float* __restrict__ e1b,
            const float* __restrict__ e2b) {
    extern __shared__ char smem[];
    const uint32_t sbm = smem_u32(smem);
    const int tid = threadIdx.x;
    const int lane = tid & 31;
    const int wid = tid >> 5;
    float* b1_s = (float*)(smem + SM_B1);
    float* b2_s = (float*)(smem + SM_B2B);

    // ---- one-time staging (single block sync) ----
#pragma unroll
    for (int it = 0; it < 16; it++) {
        int idx = tid + it * 256;
        int n = idx >> 4, c = idx & 15;
        uint4 v = *(const uint4*)(g_W2t + n * 128 + c * 8);
        *(uint4*)(smem + SM_B2 + n * 256 + ((c ^ (n & 7)) << 4)) = v;
    }
    for (int i = tid; i < 128 * 16; i += 256) {
        int n = i >> 4, k = i & 15;
        ((__nv_bfloat16*)(smem + SM_W1T))[n * 16 + k] =
            __float2bfloat16(e1W[(256 + k) * 128 + n]);
    }
    if (tid < 128) b1_s[tid] = e1b[tid];
    b2_s[tid & 255] = e2b[tid & 255];
    __syncthreads();

    const int m0 = wid * 16;
    const int r0 = lane >> 2;
    const int rowA = m0 + r0, rowB = rowA + 8;
    const int cbase = (lane & 3) * 2;
    const int tl8 = lane & 15;
    const int tsel = lane >> 3;
    const int jj_l = tsel >> 1;
    const int kh_l = tsel & 1;
    const int l7 = lane & 7;
    // warp-local staging: lane handles row m0+(lane>>1), half (lane&1)
    const int srow = m0 + (lane >> 1);
    const int shalf = lane & 1;

    for (int tile = blockIdx.x; tile < NT; tile += EGRID) {
        const long eb = (long)tile * EB;
        const int remaining = (int)(Ee - eb);

        // ---- per-row indices (lane-local) ----
        int sa = 0, da = 0, sb2 = 0, db = 0;
        const bool va = (rowA < remaining), vb = (rowB < remaining);
        if (va) { int2 ii = *(const int2*)(eidx + 2 * (eb + rowA)); sa = ii.x; da = ii.y; }
        if (vb) { int2 ii = *(const int2*)(eidx + 2 * (eb + rowB)); sb2 = ii.x; db = ii.y; }
        if ((lane & 3) == 0) {
            if (va) atomicAdd(&g_indeg[da], 1.0f);
            if (vb) atomicAdd(&g_indeg[db], 1.0f);
        }

        // ---- staging indices for this lane's staging row ----
        int2 sii = make_int2(0, 0);
        {
            long e = eb + srow;
            if (srow < remaining) sii = *(const int2*)(eidx + 2 * e);
        }

        // ---- warp-local PS staging: PS = P1[s] + P2[d] (wide, HADD2) ----
        __syncwarp();   // prior tile's epilogue S reads done
        {
            const uint4* p1 = (const uint4*)(g_P1b + (long)sii.x * Hh + shalf * 64);
            const uint4* p2 = (const uint4*)(g_P2b + (long)sii.y * Hh + shalf * 64);
            uint32_t dst = sbm + SM_S + srow * S_STRIDE + shalf * 128;
#pragma unroll
            for (int k = 0; k < 8; k++) {
                uint4 a = p1[k], b = p2[k];
                uint4 o;
                o.x = badd2(a.x, b.x); o.y = badd2(a.y, b.y);
                o.z = badd2(a.z, b.z); o.w = badd2(a.w, b.w);
                *(uint4*)(smem + (dst - sbm) + k * 16) = o;
            }
        }
        __syncwarp();   // PS visible to warp

        // ---- C1 init = b1 + PS (conflict-free LDS) ----
        const uint32_t psA = SM_S + rowA * S_STRIDE;
        const uint32_t psB = SM_S + rowB * S_STRIDE;
        float C1[16][4];
#pragma unroll
        for (int j = 0; j < 16; j++) {
            int boff = (j * 8 + cbase) * 2;
            float2 bb = *(const float2*)(b1_s + j * 8 + cbase);
            float2 pa = up2(*(const uint32_t*)(smem + psA + boff));
            float2 pb = up2(*(const uint32_t*)(smem + psB + boff));
            C1[j][0] = pa.x + bb.x; C1[j][1] = pa.y + bb.y;
            C1[j][2] = pb.x + bb.x; C1[j][3] = pb.y + bb.y;
        }
        __syncwarp();   // PS fully consumed — region free for S

        // ---- S prefetch into same region (warp-local cp.async) ----
        {
            const __nv_bfloat16* sp = g_Sb + (long)sii.x * Hh + shalf * 64;
            uint32_t dst = sbm + SM_S + srow * S_STRIDE + shalf * 128;
#pragma unroll
            for (int c = 0; c < 8; c++)
                cp_async16(dst + c * 16, sp + c * 8);
        }
        CP_COMMIT();

        // ---- warp-local EST staging ----
        {
            long e = eb + srow;
            long ec = (srow < remaining) ? e : eb;
            const float4* p = (const float4*)(eattr + ec * 16 + shalf * 8);
            float4 v0 = p[0], v1 = p[1];
            uint4 w;
            w.x = pack_bf16(v0.x, v0.y); w.y = pack_bf16(v0.z, v0.w);
            w.z = pack_bf16(v1.x, v1.y); w.w = pack_bf16(v1.z, v1.w);
            *(uint4*)(smem + SM_EST + srow * 32 + shalf * 16) = w;
        }
        __syncwarp();

        // ---- MMA1: C1 += eattr(16) @ W1e(16x128) ----
        uint32_t A1[4];
        {
            int row = m0 + ((tsel & 1) << 3) + l7;
            ldsm_x4(A1, sbm + SM_EST + row * 32 + ((tsel >> 1) << 4));
        }
#pragma unroll
        for (int j = 0; j < 16; j++) {
            uint32_t Bf[2];
            int n = j * 8 + (tl8 & 7);
            ldsm_x2(Bf, sbm + SM_W1T + n * 32 + ((tl8 >> 3) << 4));
            mma_bf16(C1[j], A1, Bf);
        }

        // ---- GELU + repack ----
        uint32_t A2[8][4];
#pragma unroll
        for (int kb = 0; kb < 8; kb++) {
            A2[kb][0] = pack_bf16(gelu_fast(C1[2 * kb][0]),     gelu_fast(C1[2 * kb][1]));
            A2[kb][1] = pack_bf16(gelu_fast(C1[2 * kb][2]),     gelu_fast(C1[2 * kb][3]));
            A2[kb][2] = pack_bf16(gelu_fast(C1[2 * kb + 1][0]), gelu_fast(C1[2 * kb + 1][1]));
            A2[kb][3] = pack_bf16(gelu_fast(C1[2 * kb + 1][2]), gelu_fast(C1[2 * kb + 1][3]));
        }

        // ---- S prefetch complete (warp-local) ----
        CP_WAIT0();
        __syncwarp();

        float* apa = g_agg + (long)da * Hh;
        float* apb = g_agg + (long)db * Hh;

#pragma unroll 1
        for (int g = 0; g < 8; g++) {
            float Cg[2][4] = {}, Cs[2][4] = {};
            const int ngl = (2 * g + jj_l) * 8 + l7;
            const int nsl = ngl + 128;
#pragma unroll
            for (int kb = 0; kb < 8; kb++) {
                uint32_t Bg[4], Bs[4];
                int c = kb * 2 + kh_l;
                ldsm_x4(Bg, sbm + SM_B2 + ngl * 256 + ((c ^ (ngl & 7)) << 4));
                ldsm_x4(Bs, sbm + SM_B2 + nsl * 256 + ((c ^ (nsl & 7)) << 4));
                mma_bf16(Cg[0], A2[kb], Bg);
                mma_bf16(Cg[1], A2[kb], Bg + 2);
                mma_bf16(Cs[0], A2[kb], Bs);
                mma_bf16(Cs[1], A2[kb], Bs + 2);
            }
#pragma unroll
            for (int jj = 0; jj < 2; jj++) {
                int c0 = (2 * g + jj) * 8 + cbase;
                float2 bg = *(const float2*)(b2_s + c0);
                float2 bsv = *(const float2*)(b2_s + 128 + c0);
                if (va) {
                    float2 sv = up2(*(const uint32_t*)(smem + psA + c0 * 2));
                    float g0 = Cg[jj][0] + bg.x, g1 = Cg[jj][1] + bg.y;
                    float s0 = Cs[jj][0] + bsv.x, s1 = Cs[jj][1] + bsv.y;
                    float v0 = sv.x * __fdividef(1.0f, 1.0f + __expf(-g0)) + s0;
                    float v1 = sv.y * __fdividef(1.0f, 1.0f + __expf(-g1)) + s1;
                    asm volatile("red.global.add.v2.f32 [%0], {%1,%2};"
                                 :: "l"(apa + c0), "f"(v0), "f"(v1) : "memory");
                }
                if (vb) {
                    float2 sv = up2(*(const uint32_t*)(smem + psB + c0 * 2));
                    float g0 = Cg[jj][2] + bg.x, g1 = Cg[jj][3] + bg.y;
                    float s0 = Cs[jj][2] + bsv.x, s1 = Cs[jj][3] + bsv.y;
                    float v0 = sv.x * __fdividef(1.0f, 1.0f + __expf(-g0)) + s0;
                    float v1 = sv.y * __fdividef(1.0f, 1.0f + __expf(-g1)) + s1;
                    asm volatile("red.global.add.v2.f32 [%0], {%1,%2};"
                                 :: "l"(apb + c0), "f"(v0), "f"(v1) : "memory");
                }
            }
        }
    }
}

// ---------------------------------------------------------------------------
// K3: node update via bf16 HMMA — 128 nodes/CTA, LN in fragments, 3 CTAs/SM.
// ---------------------------------------------------------------------------
#define NU_SM_B  0
#define NU_SM_A  32768
#define NU_SM_AB 65536
#define NU_SM_LG 66048
#define NU_SM_LB 66560
#define NU_SMEM  67072

__global__ void __launch_bounds__(256, 3)
node_up_mma(const float* __restrict__ h,
            const float* __restrict__ aggB,
            const float* __restrict__ lng,
            const float* __restrict__ lnb,
            float* __restrict__ out) {
    extern __shared__ char smem[];
    const uint32_t sbm = smem_u32(smem);
    const int tid = threadIdx.x;
    const int lane = tid & 31;
    const int wid = tid >> 5;
    const int tile = blockIdx.x;
    float* ab_s = (float*)(smem + NU_SM_AB);
    float* lg_s = (float*)(smem + NU_SM_LG);
    float* lb_s = (float*)(smem + NU_SM_LB);

#pragma unroll
    for (int it = 0; it < 8; it++) {
        int idx = tid + it * 256;
        int row = idx >> 4, c = idx & 15;
        int node = tile * 128 + row;
        uint4 w = make_uint4(0u, 0u, 0u, 0u);
        if (node < Nn) {
            float rd = 1.0f / fmaxf(g_indeg[node], 1.0f);
            const float4* p = (const float4*)(g_agg + (long)node * 128 + c * 8);
            float4 v0 = p[0], v1 = p[1];
            w.x = pack_bf16(v0.x * rd, v0.y * rd);
            w.y = pack_bf16(v0.z * rd, v0.w * rd);
            w.z = pack_bf16(v1.x * rd, v1.y * rd);
            w.w = pack_bf16(v1.z * rd, v1.w * rd);
        }
        *(uint4*)(smem + NU_SM_A + row * 256 + ((c ^ (row & 7)) << 4)) = w;
    }
#pragma unroll
    for (int it = 0; it < 8; it++) {
        int idx = tid + it * 256;
        int n = idx >> 4, c = idx & 15;
        uint4 v = *(const uint4*)(g_WAt + (long)n * 128 + c * 8);
        *(uint4*)(smem + NU_SM_B + n * 256 + ((c ^ (n & 7)) << 4)) = v;
    }
    if (tid < 128) {
        ab_s[tid] = aggB[tid];
        lg_s[tid] = lng[tid];
        lb_s[tid] = lnb[tid];
    }
    __syncthreads();

    uint32_t Af[8][4];
    {
        int ts = lane >> 3;
        int row = wid * 16 + ((ts & 1) << 3) + (lane & 7);
        int rx = row & 7;
        uint32_t rb = sbm + NU_SM_A + row * 256;
#pragma unroll
        for (int kb = 0; kb < 8; kb++) {
            int c = kb * 2 + (ts >> 1);
            ldsm_x4(Af[kb], rb + ((c ^ rx) << 4));
        }
    }

    const int tsel = lane >> 3;
    const int jj_l = tsel >> 1;
    const int kh_l = tsel & 1;
    const int l7 = lane & 7;
    const int r0 = lane >> 2;
    const int cb2 = (lane & 3) * 2;

    float CT[16][4];
#pragma unroll
    for (int j = 0; j < 16; j++) {
        CT[j][0] = 0.f; CT[j][1] = 0.f; CT[j][2] = 0.f; CT[j][3] = 0.f;
    }
#pragma unroll 1
    for (int p = 0; p < 8; p++) {
        const int ng = p * 16 + jj_l * 8 + l7;
#pragma unroll
        for (int kb = 0; kb < 8; kb++) {
            uint32_t Bf[4];
            int c = kb * 2 + kh_l;
            ldsm_x4(Bf, sbm + NU_SM_B + ng * 256 + ((c ^ (ng & 7)) << 4));
            mma_bf16(CT[2 * p],     Af[kb], Bf);
            mma_bf16(CT[2 * p + 1], Af[kb], Bf + 2);
        }
    }

    const int rowA = wid * 16 + r0, rowB = rowA + 8;
    const int nA = tile * 128 + rowA, nB = tile * 128 + rowB;
    const bool vA = (nA < Nn), vB = (nB < Nn);
    const float* selfA = g_self + (long)nA * 128;
    const float* selfB = g_self + (long)nB * 128;
    const float* hA = h + (long)nA * 128;
    const float* hB = h + (long)nB * 128;

    float smA = 0.f, s2A = 0.f, smB = 0.f, s2B = 0.f;
#pragma unroll
    for (int j = 0; j < 16; j++) {
        int c0 = j * 8 + cb2;
        float2 ab = *(const float2*)(ab_s + c0);
        if (vA) {
            float2 sv = *(const float2*)(selfA + c0);
            float2 hv = *(const float2*)(hA + c0);
            float x0 = hv.x + gelu_fast(sv.x + CT[j][0] + ab.x);
            float x1 = hv.y + gelu_fast(sv.y + CT[j][1] + ab.y);
            CT[j][0] = x0; CT[j][1] = x1;
            smA += x0 + x1; s2A += x0 * x0 + x1 * x1;
        }
        if (vB) {
            float2 sv = *(const float2*)(selfB + c0);
            float2 hv = *(const float2*)(hB + c0);
            float x0 = hv.x + gelu_fast(sv.x + CT[j][2] + ab.x);
            float x1 = hv.y + gelu_fast(sv.y + CT[j][3] + ab.y);
            CT[j][2] = x0; CT[j][3] = x1;
            smB += x0 + x1; s2B += x0 * x0 + x1 * x1;
        }
    }
#pragma unroll
    for (int o = 1; o < 4; o <<= 1) {
        smA += __shfl_xor_sync(0xffffffff, smA, o);
        s2A += __shfl_xor_sync(0xffffffff, s2A, o);
        smB += __shfl_xor_sync(0xffffffff, smB, o);
        s2B += __shfl_xor_sync(0xffffffff, s2B, o);
    }
    float muA = smA * (1.0f / Hh);
    float rstdA = rsqrtf(s2A * (1.0f / Hh) - muA * muA + LN_EPS);
    float muB = smB * (1.0f / Hh);
    float rstdB = rsqrtf(s2B * (1.0f / Hh) - muB * muB + LN_EPS);

    float* outA = out + (long)nA * 128;
    float* outB = out + (long)nB * 128;
#pragma unroll
    for (int j = 0; j < 16; j++) {
        int c0 = j * 8 + cb2;
        float2 g = *(const float2*)(lg_s + c0);
        float2 b = *(const float2*)(lb_s + c0);
        if (vA) {
            float2 o;
            o.x = (CT[j][0] - muA) * rstdA * g.x + b.x;
            o.y = (CT[j][1] - muA) * rstdA * g.y + b.y;
            *(float2*)(outA + c0) = o;
        }
        if (vB) {
            float2 o;
            o.x = (CT[j][2] - muB) * rstdB * g.x + b.x;
            o.y = (CT[j][3] - muB) * rstdB * g.y + b.y;
            *(float2*)(outB + c0) = o;
        }
    }
}

// ---------------------------------------------------------------------------
extern "C" void kernel_launch(void* const* d_in, const int* in_sizes, int n_in,
                              void* d_out, int out_size) {
    const float* h     = (const float*)d_in[0];
    const float* eattr = (const float*)d_in[1];
    const int*   eidx  = (const int*)d_in[2];
    const float* srcW  = (const float*)d_in[3];
    const float* srcB  = (const float*)d_in[4];
    const float* e1W   = (const float*)d_in[5];
    const float* e1b   = (const float*)d_in[6];
    const float* e2W   = (const float*)d_in[7];
    const float* e2b   = (const float*)d_in[8];
    const float* selfW = (const float*)d_in[9];
    const float* selfB = (const float*)d_in[10];
    const float* aggW  = (const float*)d_in[11];
    const float* aggB  = (const float*)d_in[12];
    const float* lng   = (const float*)d_in[13];
    const float* lnb   = (const float*)d_in[14];
    float* out = (float*)d_out;

    cudaFuncSetAttribute(edge_kernel, cudaFuncAttributeMaxDynamicSharedMemorySize, SMEM_EDGE);
    cudaFuncSetAttribute(node_pre_mma, cudaFuncAttributeMaxDynamicSharedMemorySize, NP_SMEM);
    cudaFuncSetAttribute(node_up_mma, cudaFuncAttributeMaxDynamicSharedMemorySize, NU_SMEM);

    long pz_elems = (long)Nn * Hh / 4 + Nn / 4;
    prep_zero_kernel<<<(int)((pz_elems + 255) / 256), 256>>>(e2W, e1W, srcW, selfW, srcB, selfB, aggW);
    node_pre_mma<<<dim3((Nn + 127) / 128, 2), 256, NP_SMEM>>>(h);
    edge_kernel<<<EGRID, 256, SMEM_EDGE>>>(eattr, eidx, e1W, e1b, e2b);
    node_up_mma<<<(Nn + 127) / 128, 256, NU_SMEM>>>(h, aggB, lng, lnb, out);
}

// round 17
// speedup vs baseline: 1.1061x; 1.1061x over previous
#include <cuda_runtime.h>
#include <cuda_bf16.h>
#include <math.h>
#include <cstdint>

#define Hh 128
#define Nn 50000
#define Ee 500000
#define LN_EPS 1e-5f
#define EB 128
#define NT ((Ee + EB - 1) / EB)     // 3907 tiles
#define EGRID 296

// ---------------- scratch ----------------
__device__ __align__(16) __nv_bfloat16 g_P1b[Nn * Hh];
__device__ __align__(16) __nv_bfloat16 g_P2b[Nn * Hh];
__device__ __align__(16) __nv_bfloat16 g_Sb[Nn * Hh];
__device__ float g_self[Nn * Hh];
__device__ float g_agg[Nn * Hh];
__device__ float g_indeg[Nn];
__device__ __align__(16) __nv_bfloat16 g_W2t[256 * 128];
__device__ __align__(16) __nv_bfloat16 g_Wn[512 * 128];
__device__ __align__(16) __nv_bfloat16 g_WAt[128 * 128];   // aggW^T bf16 [n][k]
__device__ float g_bn[512];

// Branchless erf (Abramowitz–Stegun 7.1.26, |err| <= 1.5e-7)
__device__ __forceinline__ float gelu_fast(float x) {
    float z = x * 0.70710678118654752440f;
    float az = fabsf(z);
    float t = __fdividef(1.0f, fmaf(0.3275911f, az, 1.0f));
    float p = t * fmaf(t, fmaf(t, fmaf(t, fmaf(t, 1.061405429f, -1.453152027f),
                                       1.421413741f), -0.284496736f), 0.254829592f);
    float e = __expf(-z * z);
    float erf_abs = fmaf(-p, e, 1.0f);
    float erfv = copysignf(erf_abs, z);
    return 0.5f * x * (1.0f + erfv);
}

__device__ __forceinline__ uint32_t smem_u32(const void* p) {
    uint32_t a;
    asm("{ .reg .u64 t; cvta.to.shared.u64 t, %1; cvt.u32.u64 %0, t; }" : "=r"(a) : "l"(p));
    return a;
}
__device__ __forceinline__ void ldsm_x4(uint32_t* r, uint32_t addr) {
    asm volatile("ldmatrix.sync.aligned.m8n8.x4.shared.b16 {%0,%1,%2,%3}, [%4];"
                 : "=r"(r[0]), "=r"(r[1]), "=r"(r[2]), "=r"(r[3]) : "r"(addr));
}
__device__ __forceinline__ void ldsm_x2(uint32_t* r, uint32_t addr) {
    asm volatile("ldmatrix.sync.aligned.m8n8.x2.shared.b16 {%0,%1}, [%2];"
                 : "=r"(r[0]), "=r"(r[1]) : "r"(addr));
}
__device__ __forceinline__ void mma_bf16(float* c, const uint32_t* a, const uint32_t* b) {
    asm volatile(
        "mma.sync.aligned.m16n8k16.row.col.f32.bf16.bf16.f32 "
        "{%0,%1,%2,%3},{%4,%5,%6,%7},{%8,%9},{%0,%1,%2,%3};"
        : "+f"(c[0]), "+f"(c[1]), "+f"(c[2]), "+f"(c[3])
        : "r"(a[0]), "r"(a[1]), "r"(a[2]), "r"(a[3]), "r"(b[0]), "r"(b[1]));
}
__device__ __forceinline__ void mma_bf16_b2(float* c, const uint32_t* a,
                                            uint32_t b0, uint32_t b1) {
    asm volatile(
        "mma.sync.aligned.m16n8k16.row.col.f32.bf16.bf16.f32 "
        "{%0,%1,%2,%3},{%4,%5,%6,%7},{%8,%9},{%0,%1,%2,%3};"
        : "+f"(c[0]), "+f"(c[1]), "+f"(c[2]), "+f"(c[3])
        : "r"(a[0]), "r"(a[1]), "r"(a[2]), "r"(a[3]), "r"(b0), "r"(b1));
}
__device__ __forceinline__ uint32_t pack_bf16(float a, float b) {
    __nv_bfloat162 t = __float22bfloat162_rn(make_float2(a, b));
    return *reinterpret_cast<uint32_t*>(&t);
}
__device__ __forceinline__ float2 bf2f(const __nv_bfloat16* p) {
    return __bfloat1622float2(*(const __nv_bfloat162*)p);
}
__device__ __forceinline__ float2 up2(uint32_t v) {
    return __bfloat1622float2(*reinterpret_cast<__nv_bfloat162*>(&v));
}
__device__ __forceinline__ void cp_async16(uint32_t dst, const void* src) {
    asm volatile("cp.async.cg.shared.global [%0], [%1], 16;" :: "r"(dst), "l"(src) : "memory");
}
#define CP_COMMIT() asm volatile("cp.async.commit_group;" ::: "memory")
#define CP_WAIT0()  asm volatile("cp.async.wait_group 0;" ::: "memory")

// ---------------------------------------------------------------------------
// prep + zero fused
// ---------------------------------------------------------------------------
__global__ void prep_zero_kernel(const float* __restrict__ e2W,
                                 const float* __restrict__ e1W,
                                 const float* __restrict__ srcW,
                                 const float* __restrict__ selfW,
                                 const float* __restrict__ srcB,
                                 const float* __restrict__ selfB,
                                 const float* __restrict__ aggW) {
    long i = (long)blockIdx.x * 256 + threadIdx.x;
    const long agg4 = (long)Nn * Hh / 4;
    if (i < agg4) ((float4*)g_agg)[i] = make_float4(0.f, 0.f, 0.f, 0.f);
    else if (i < agg4 + Nn / 4) ((float4*)g_indeg)[i - agg4] = make_float4(0.f, 0.f, 0.f, 0.f);

    if (i < 512 * 128) {
        int n = (int)i >> 7, k = (int)i & 127;
        float v;
        if (n < 128)      v = e1W[k * 128 + n];
        else if (n < 256) v = e1W[(128 + k) * 128 + (n - 128)];
        else if (n < 384) v = srcW[k * 128 + (n - 256)];
        else              v = selfW[k * 128 + (n - 384)];
        g_Wn[i] = __float2bfloat16(v);
    }
    if (i < 256 * 128) {
        int n = (int)i >> 7, k = (int)i & 127;
        g_W2t[i] = __float2bfloat16(e2W[k * 256 + n]);
    }
    if (i < 128 * 128) {
        int n = (int)i >> 7, k = (int)i & 127;
        g_WAt[i] = __float2bfloat16(aggW[k * 128 + n]);
    }
    if (i < 512) {
        g_bn[i] = (i < 256) ? 0.0f : ((i < 384) ? srcB[i - 256] : selfB[i - 384]);
    }
}

// ---------------------------------------------------------------------------
// K1: node projections via bf16 HMMA (unchanged)
// ---------------------------------------------------------------------------
#define NP_SM_A 0
#define NP_SM_B 32768
#define NP_SM_BI 98304
#define NP_SMEM 99328

__global__ void __launch_bounds__(256, 2)
node_pre_mma(const float* __restrict__ h) {
    extern __shared__ char smem[];
    const uint32_t sbm = smem_u32(smem);
    const int tid = threadIdx.x;
    const int lane = tid & 31;
    const int wid = tid >> 5;
    const int tile = blockIdx.x;
    const int half = blockIdx.y;
    float* bi_s = (float*)(smem + NP_SM_BI);

#pragma unroll
    for (int it = 0; it < 8; it++) {
        int idx = tid + it * 256;
        int row = idx >> 4, c = idx & 15;
        int node = tile * 128 + row;
        uint4 w = make_uint4(0u, 0u, 0u, 0u);
        if (node < Nn) {
            const float4* p = (const float4*)(h + (long)node * 128 + c * 8);
            float4 v0 = p[0], v1 = p[1];
            w.x = pack_bf16(v0.x, v0.y); w.y = pack_bf16(v0.z, v0.w);
            w.z = pack_bf16(v1.x, v1.y); w.w = pack_bf16(v1.z, v1.w);
        }
        *(uint4*)(smem + NP_SM_A + row * 256 + ((c ^ (row & 7)) << 4)) = w;
    }
#pragma unroll
    for (int it = 0; it < 16; it++) {
        int idx = tid + it * 256;
        int n = idx >> 4, c = idx & 15;
        uint4 v = *(const uint4*)(g_Wn + (long)(half * 256 + n) * 128 + c * 8);
        *(uint4*)(smem + NP_SM_B + n * 256 + ((c ^ (n & 7)) << 4)) = v;
    }
    if (tid < 256) bi_s[tid] = g_bn[half * 256 + tid];
    __syncthreads();

    uint32_t Af[8][4];
    {
        int ts = lane >> 3;
        int row = wid * 16 + ((ts & 1) << 3) + (lane & 7);
        int rx = row & 7;
        uint32_t rb = sbm + NP_SM_A + row * 256;
#pragma unroll
        for (int kb = 0; kb < 8; kb++) {
            int c = kb * 2 + (ts >> 1);
            ldsm_x4(Af[kb], rb + ((c ^ rx) << 4));
        }
    }

    const int tsel = lane >> 3;
    const int jj_l = tsel >> 1;
    const int kh_l = tsel & 1;
    const int l7 = lane & 7;
    const int r0 = lane >> 2;
    const int cb2 = (lane & 3) * 2;

#pragma unroll 1
    for (int p = 0; p < 16; p++) {
        float C[2][4] = {{0.f,0.f,0.f,0.f},{0.f,0.f,0.f,0.f}};
        const int ng = p * 16 + jj_l * 8 + l7;
#pragma unroll
        for (int kb = 0; kb < 8; kb++) {
            uint32_t Bf[4];
            int c = kb * 2 + kh_l;
            ldsm_x4(Bf, sbm + NP_SM_B + ng * 256 + ((c ^ (ng & 7)) << 4));
            mma_bf16(C[0], Af[kb], Bf);
            mma_bf16(C[1], Af[kb], Bf + 2);
        }
#pragma unroll
        for (int jj = 0; jj < 2; jj++) {
            int nl = (2 * p + jj) * 8 + cb2;
            int n = half * 256 + nl;
            float2 bias = *(const float2*)(bi_s + nl);
            int nm = n & 127;
#pragma unroll
            for (int rh = 0; rh < 2; rh++) {
                int row = wid * 16 + r0 + rh * 8;
                int node = tile * 128 + row;
                if (node < Nn) {
                    float v0 = C[jj][rh * 2] + bias.x;
                    float v1 = C[jj][rh * 2 + 1] + bias.y;
                    if (n < 384) {
                        __nv_bfloat16* dstb = (n < 128) ? g_P1b : (n < 256) ? g_P2b : g_Sb;
                        *(__nv_bfloat162*)(dstb + (long)node * 128 + nm) =
                            __float22bfloat162_rn(make_float2(v0, v1));
                    } else {
                        *(float2*)(g_self + (long)node * 128 + nm) = make_float2(v0, v1);
                    }
                }
            }
        }
    }
}

// ---------------------------------------------------------------------------
// K2: persistent edge kernel — warp-decoupled main loop (R15 structure).
// EST staged warp-locally, S prefetch warp-local cp.async, gathers lane-local.
// MMA1 W1T B-frags via 8 ldsm_x4 (covers n-tile pairs).
// smem: B2 65536 @0 ; W1T 4096 @65536 ; EST 4096 @69632 ; b1 512 @73728 ;
//       b2 1024 @74240 ; S 128x272 @75264 (34816) -> 110080
// ---------------------------------------------------------------------------
#define SM_B2   0
#define SM_W1T  65536
#define SM_EST  69632
#define SM_B1   73728
#define SM_B2B  74240
#define SM_S    75264
#define S_STRIDE 272
#define SMEM_EDGE 110080

__global__ void __launch_bounds__(256, 2)
edge_kernel(const float* __restrict__ eattr,
            const int* __restrict__ eidx,
            const float* __restrict__ e1W,
            const float* __restrict__ e1b,
            const float* __restrict__ e2b) {
    extern __shared__ char smem[];
    const uint32_t sbm = smem_u32(smem);
    const int tid = threadIdx.x;
    const int lane = tid & 31;
    const int wid = tid >> 5;
    float* b1_s = (float*)(smem + SM_B1);
    float* b2_s = (float*)(smem + SM_B2B);

    // ---- one-time staging (single block sync) ----
#pragma unroll
    for (int it = 0; it < 16; it++) {
        int idx = tid + it * 256;
        int n = idx >> 4, c = idx & 15;
        uint4 v = *(const uint4*)(g_W2t + n * 128 + c * 8);
        *(uint4*)(smem + SM_B2 + n * 256 + ((c ^ (n & 7)) << 4)) = v;
    }
    for (int i = tid; i < 128 * 16; i += 256) {
        int n = i >> 4, k = i & 15;
        ((__nv_bfloat16*)(smem + SM_W1T))[n * 16 + k] =
            __float2bfloat16(e1W[(256 + k) * 128 + n]);
    }
    if (tid < 128) b1_s[tid] = e1b[tid];
    b2_s[tid & 255] = e2b[tid & 255];
    __syncthreads();

    const int m0 = wid * 16;
    const int r0 = lane >> 2;
    const int rowA = m0 + r0, rowB = rowA + 8;
    const int cbase = (lane & 3) * 2;
    const int tsel = lane >> 3;
    const int jj_l = tsel >> 1;
    const int kh_l = tsel & 1;
    const int l7 = lane & 7;
    // warp-local staging assignments (each warp owns rows m0..m0+15)
    const int srow = m0 + (lane >> 1);     // EST & S row for this lane
    const int shalf = lane & 1;
    // MMA1 x4 B-load addressing: rows n = j*16 + (lane&15), chunk (lane>>4)
    const uint32_t w1t_addr_base = sbm + SM_W1T + (lane & 15) * 32 + ((lane >> 4) << 4);

    for (int tile = blockIdx.x; tile < NT; tile += EGRID) {
        const long eb = (long)tile * EB;
        const int remaining = (int)(Ee - eb);

        // ---- per-row indices (lane-local) ----
        int sa = 0, da = 0, sb2 = 0, db = 0;
        const bool va = (rowA < remaining), vb = (rowB < remaining);
        if (va) { int2 ii = *(const int2*)(eidx + 2 * (eb + rowA)); sa = ii.x; da = ii.y; }
        if (vb) { int2 ii = *(const int2*)(eidx + 2 * (eb + rowB)); sb2 = ii.x; db = ii.y; }
        if ((lane & 3) == 0) {
            if (va) atomicAdd(&g_indeg[da], 1.0f);
            if (vb) atomicAdd(&g_indeg[db], 1.0f);
        }

        // ---- warp-local S prefetch (cp.async) ----
        {
            long e = eb + srow;
            int sidx = (srow < remaining) ? eidx[2 * e] : 0;
            const __nv_bfloat16* sp = g_Sb + (long)sidx * Hh + shalf * 64;
            uint32_t dst = sbm + SM_S + srow * S_STRIDE + shalf * 128;
#pragma unroll
            for (int c = 0; c < 8; c++)
                cp_async16(dst + c * 16, sp + c * 8);
        }
        CP_COMMIT();

        // ---- warp-local EST staging ----
        __syncwarp();
        {
            long e = eb + srow;
            long ec = (srow < remaining) ? e : eb;
            const float4* p = (const float4*)(eattr + ec * 16 + shalf * 8);
            float4 v0 = p[0], v1 = p[1];
            uint4 w;
            w.x = pack_bf16(v0.x, v0.y); w.y = pack_bf16(v0.z, v0.w);
            w.z = pack_bf16(v1.x, v1.y); w.w = pack_bf16(v1.z, v1.w);
            *(uint4*)(smem + SM_EST + srow * 32 + shalf * 16) = w;
        }
        __syncwarp();

        // ---- C1 = b1 (broadcast), then MMA1 (smem-only, x4 B-loads) ----
        float C1[16][4];
#pragma unroll
        for (int j = 0; j < 16; j++) {
            float2 bb = *(const float2*)(b1_s + j * 8 + cbase);
            C1[j][0] = bb.x; C1[j][1] = bb.y;
            C1[j][2] = bb.x; C1[j][3] = bb.y;
        }
        uint32_t A1[4];
        {
            int row = m0 + ((tsel & 1) << 3) + l7;
            ldsm_x4(A1, sbm + SM_EST + row * 32 + ((tsel >> 1) << 4));
        }
#pragma unroll
        for (int j = 0; j < 8; j++) {
            uint32_t Bf[4];
            ldsm_x4(Bf, w1t_addr_base + j * 16 * 32);
            mma_bf16_b2(C1[2 * j],     A1, Bf[0], Bf[2]);
            mma_bf16_b2(C1[2 * j + 1], A1, Bf[1], Bf[3]);
        }

        // ---- gather-adds: C1 += P1[s] + P2[d] ----
        const __nv_bfloat16* p1a = g_P1b + (long)sa * Hh;
        const __nv_bfloat16* p2a = g_P2b + (long)da * Hh;
        const __nv_bfloat16* p1b = g_P1b + (long)sb2 * Hh;
        const __nv_bfloat16* p2b = g_P2b + (long)db * Hh;
#pragma unroll
        for (int j = 0; j < 16; j++) {
            int c = j * 8 + cbase;
            float2 x1 = bf2f(p1a + c);
            float2 x2 = bf2f(p2a + c);
            float2 y1 = bf2f(p1b + c);
            float2 y2 = bf2f(p2b + c);
            C1[j][0] += x1.x + x2.x; C1[j][1] += x1.y + x2.y;
            C1[j][2] += y1.x + y2.x; C1[j][3] += y1.y + y2.y;
        }

        // ---- GELU + repack ----
        uint32_t A2[8][4];
#pragma unroll
        for (int kb = 0; kb < 8; kb++) {
            A2[kb][0] = pack_bf16(gelu_fast(C1[2 * kb][0]),     gelu_fast(C1[2 * kb][1]));
            A2[kb][1] = pack_bf16(gelu_fast(C1[2 * kb][2]),     gelu_fast(C1[2 * kb][3]));
            A2[kb][2] = pack_bf16(gelu_fast(C1[2 * kb + 1][0]), gelu_fast(C1[2 * kb + 1][1]));
            A2[kb][3] = pack_bf16(gelu_fast(C1[2 * kb + 1][2]), gelu_fast(C1[2 * kb + 1][3]));
        }

        // ---- S prefetch complete (warp-local) ----
        CP_WAIT0();
        __syncwarp();
        const uint32_t sA_base = sbm + SM_S + rowA * S_STRIDE;
        const uint32_t sB_base = sbm + SM_S + rowB * S_STRIDE;

        float* apa = g_agg + (long)da * Hh;
        float* apb = g_agg + (long)db * Hh;

#pragma unroll 1
        for (int g = 0; g < 8; g++) {
            float Cg[2][4] = {}, Cs[2][4] = {};
            const int ngl = (2 * g + jj_l) * 8 + l7;
            const int nsl = ngl + 128;
#pragma unroll
            for (int kb = 0; kb < 8; kb++) {
                uint32_t Bg[4], Bs[4];
                int c = kb * 2 + kh_l;
                ldsm_x4(Bg, sbm + SM_B2 + ngl * 256 + ((c ^ (ngl & 7)) << 4));
                ldsm_x4(Bs, sbm + SM_B2 + nsl * 256 + ((c ^ (nsl & 7)) << 4));
                mma_bf16(Cg[0], A2[kb], Bg);
                mma_bf16(Cg[1], A2[kb], Bg + 2);
                mma_bf16(Cs[0], A2[kb], Bs);
                mma_bf16(Cs[1], A2[kb], Bs + 2);
            }
#pragma unroll
            for (int jj = 0; jj < 2; jj++) {
                int c0 = (2 * g + jj) * 8 + cbase;
                float2 bg = *(const float2*)(b2_s + c0);
                float2 bsv = *(const float2*)(b2_s + 128 + c0);
                if (va) {
                    float2 sv = up2(*(const uint32_t*)(smem + (sA_base - sbm) + c0 * 2));
                    float g0 = Cg[jj][0] + bg.x, g1 = Cg[jj][1] + bg.y;
                    float s0 = Cs[jj][0] + bsv.x, s1 = Cs[jj][1] + bsv.y;
                    float v0 = sv.x * __fdividef(1.0f, 1.0f + __expf(-g0)) + s0;
                    float v1 = sv.y * __fdividef(1.0f, 1.0f + __expf(-g1)) + s1;
                    asm volatile("red.global.add.v2.f32 [%0], {%1,%2};"
                                 :: "l"(apa + c0), "f"(v0), "f"(v1) : "memory");
                }
                if (vb) {
                    float2 sv = up2(*(const uint32_t*)(smem + (sB_base - sbm) + c0 * 2));
                    float g0 = Cg[jj][2] + bg.x, g1 = Cg[jj][3] + bg.y;
                    float s0 = Cs[jj][2] + bsv.x, s1 = Cs[jj][3] + bsv.y;
                    float v0 = sv.x * __fdividef(1.0f, 1.0f + __expf(-g0)) + s0;
                    float v1 = sv.y * __fdividef(1.0f, 1.0f + __expf(-g1)) + s1;
                    asm volatile("red.global.add.v2.f32 [%0], {%1,%2};"
                                 :: "l"(apb + c0), "f"(v0), "f"(v1) : "memory");
                }
            }
        }
    }
}

// ---------------------------------------------------------------------------
// K3: node update via bf16 HMMA — 128 nodes/CTA, LN in fragments, 3 CTAs/SM.
// ---------------------------------------------------------------------------
#define NU_SM_B  0
#define NU_SM_A  32768
#define NU_SM_AB 65536
#define NU_SM_LG 66048
#define NU_SM_LB 66560
#define NU_SMEM  67072

__global__ void __launch_bounds__(256, 3)
node_up_mma(const float* __restrict__ h,
            const float* __restrict__ aggB,
            const float* __restrict__ lng,
            const float* __restrict__ lnb,
            float* __restrict__ out) {
    extern __shared__ char smem[];
    const uint32_t sbm = smem_u32(smem);
    const int tid = threadIdx.x;
    const int lane = tid & 31;
    const int wid = tid >> 5;
    const int tile = blockIdx.x;
    float* ab_s = (float*)(smem + NU_SM_AB);
    float* lg_s = (float*)(smem + NU_SM_LG);
    float* lb_s = (float*)(smem + NU_SM_LB);

#pragma unroll
    for (int it = 0; it < 8; it++) {
        int idx = tid + it * 256;
        int row = idx >> 4, c = idx & 15;
        int node = tile * 128 + row;
        uint4 w = make_uint4(0u, 0u, 0u, 0u);
        if (node < Nn) {
            float rd = 1.0f / fmaxf(g_indeg[node], 1.0f);
            const float4* p = (const float4*)(g_agg + (long)node * 128 + c * 8);
            float4 v0 = p[0], v1 = p[1];
            w.x = pack_bf16(v0.x * rd, v0.y * rd);
            w.y = pack_bf16(v0.z * rd, v0.w * rd);
            w.z = pack_bf16(v1.x * rd, v1.y * rd);
            w.w = pack_bf16(v1.z * rd, v1.w * rd);
        }
        *(uint4*)(smem + NU_SM_A + row * 256 + ((c ^ (row & 7)) << 4)) = w;
    }
#pragma unroll
    for (int it = 0; it < 8; it++) {
        int idx = tid + it * 256;
        int n = idx >> 4, c = idx & 15;
        uint4 v = *(const uint4*)(g_WAt + (long)n * 128 + c * 8);
        *(uint4*)(smem + NU_SM_B + n * 256 + ((c ^ (n & 7)) << 4)) = v;
    }
    if (tid < 128) {
        ab_s[tid] = aggB[tid];
        lg_s[tid] = lng[tid];
        lb_s[tid] = lnb[tid];
    }
    __syncthreads();

    uint32_t Af[8][4];
    {
        int ts = lane >> 3;
        int row = wid * 16 + ((ts & 1) << 3) + (lane & 7);
        int rx = row & 7;
        uint32_t rb = sbm + NU_SM_A + row * 256;
#pragma unroll
        for (int kb = 0; kb < 8; kb++) {
            int c = kb * 2 + (ts >> 1);
            ldsm_x4(Af[kb], rb + ((c ^ rx) << 4));
        }
    }

    const int tsel = lane >> 3;
    const int jj_l = tsel >> 1;
    const int kh_l = tsel & 1;
    const int l7 = lane & 7;
    const int r0 = lane >> 2;
    const int cb2 = (lane & 3) * 2;

    float CT[16][4];
#pragma unroll
    for (int j = 0; j < 16; j++) {
        CT[j][0] = 0.f; CT[j][1] = 0.f; CT[j][2] = 0.f; CT[j][3] = 0.f;
    }
#pragma unroll 1
    for (int p = 0; p < 8; p++) {
        const int ng = p * 16 + jj_l * 8 + l7;
#pragma unroll
        for (int kb = 0; kb < 8; kb++) {
            uint32_t Bf[4];
            int c = kb * 2 + kh_l;
            ldsm_x4(Bf, sbm + NU_SM_B + ng * 256 + ((c ^ (ng & 7)) << 4));
            mma_bf16(CT[2 * p],     Af[kb], Bf);
            mma_bf16(CT[2 * p + 1], Af[kb], Bf + 2);
        }
    }

    const int rowA = wid * 16 + r0, rowB = rowA + 8;
    const int nA = tile * 128 + rowA, nB = tile * 128 + rowB;
    const bool vA = (nA < Nn), vB = (nB < Nn);
    const float* selfA = g_self + (long)nA * 128;
    const float* selfB = g_self + (long)nB * 128;
    const float* hA = h + (long)nA * 128;
    const float* hB = h + (long)nB * 128;

    float smA = 0.f, s2A = 0.f, smB = 0.f, s2B = 0.f;
#pragma unroll
    for (int j = 0; j < 16; j++) {
        int c0 = j * 8 + cb2;
        float2 ab = *(const float2*)(ab_s + c0);
        if (vA) {
            float2 sv = *(const float2*)(selfA + c0);
            float2 hv = *(const float2*)(hA + c0);
            float x0 = hv.x + gelu_fast(sv.x + CT[j][0] + ab.x);
            float x1 = hv.y + gelu_fast(sv.y + CT[j][1] + ab.y);
            CT[j][0] = x0; CT[j][1] = x1;
            smA += x0 + x1; s2A += x0 * x0 + x1 * x1;
        }
        if (vB) {
            float2 sv = *(const float2*)(selfB + c0);
            float2 hv = *(const float2*)(hB + c0);
            float x0 = hv.x + gelu_fast(sv.x + CT[j][2] + ab.x);
            float x1 = hv.y + gelu_fast(sv.y + CT[j][3] + ab.y);
            CT[j][2] = x0; CT[j][3] = x1;
            smB += x0 + x1; s2B += x0 * x0 + x1 * x1;
        }
    }
#pragma unroll
    for (int o = 1; o < 4; o <<= 1) {
        smA += __shfl_xor_sync(0xffffffff, smA, o);
        s2A += __shfl_xor_sync(0xffffffff, s2A, o);
        smB += __shfl_xor_sync(0xffffffff, smB, o);
        s2B += __shfl_xor_sync(0xffffffff, s2B, o);
    }
    float muA = smA * (1.0f / Hh);
    float rstdA = rsqrtf(s2A * (1.0f / Hh) - muA * muA + LN_EPS);
    float muB = smB * (1.0f / Hh);
    float rstdB = rsqrtf(s2B * (1.0f / Hh) - muB * muB + LN_EPS);

    float* outA = out + (long)nA * 128;
    float* outB = out + (long)nB * 128;
#pragma unroll
    for (int j = 0; j < 16; j++) {
        int c0 = j * 8 + cb2;
        float2 g = *(const float2*)(lg_s + c0);
        float2 b = *(const float2*)(lb_s + c0);
        if (vA) {
            float2 o;
            o.x = (CT[j][0] - muA) * rstdA * g.x + b.x;
            o.y = (CT[j][1] - muA) * rstdA * g.y + b.y;
            *(float2*)(outA + c0) = o;
        }
        if (vB) {
            float2 o;
            o.x = (CT[j][2] - muB) * rstdB * g.x + b.x;
            o.y = (CT[j][3] - muB) * rstdB * g.y + b.y;
            *(float2*)(outB + c0) = o;
        }
    }
}

// ---------------------------------------------------------------------------
extern "C" void kernel_launch(void* const* d_in, const int* in_sizes, int n_in,
                              void* d_out, int out_size) {
    const float* h     = (const float*)d_in[0];
    const float* eattr = (const float*)d_in[1];
    const int*   eidx  = (const int*)d_in[2];
    const float* srcW  = (const float*)d_in[3];
    const float* srcB  = (const float*)d_in[4];
    const float* e1W   = (const float*)d_in[5];
    const float* e1b   = (const float*)d_in[6];
    const float* e2W   = (const float*)d_in[7];
    const float* e2b   = (const float*)d_in[8];
    const float* selfW = (const float*)d_in[9];
    const float* selfB = (const float*)d_in[10];
    const float* aggW  = (const float*)d_in[11];
    const float* aggB  = (const float*)d_in[12];
    const float* lng   = (const float*)d_in[13];
    const float* lnb   = (const float*)d_in[14];
    float* out = (float*)d_out;

    cudaFuncSetAttribute(edge_kernel, cudaFuncAttributeMaxDynamicSharedMemorySize, SMEM_EDGE);
    cudaFuncSetAttribute(node_pre_mma, cudaFuncAttributeMaxDynamicSharedMemorySize, NP_SMEM);
    cudaFuncSetAttribute(node_up_mma, cudaFuncAttributeMaxDynamicSharedMemorySize, NU_SMEM);

    long pz_elems = (long)Nn * Hh / 4 + Nn / 4;
    prep_zero_kernel<<<(int)((pz_elems + 255) / 256), 256>>>(e2W, e1W, srcW, selfW, srcB, selfB, aggW);
    node_pre_mma<<<dim3((Nn + 127) / 128, 2), 256, NP_SMEM>>>(h);
    edge_kernel<<<EGRID, 256, SMEM_EDGE>>>(eattr, eidx, e1W, e1b, e2b);
    node_up_mma<<<(Nn + 127) / 128, 256, NU_SMEM>>>(h, aggB, lng, lnb, out);
}